// round 2
// baseline (speedup 1.0000x reference)
#include <cuda_runtime.h>
#include <math.h>

// ---------------- problem constants ----------------
#define S_TOK   128
#define T_TOK   32768
#define KW      1024      // window / fourier size == LSTM input size
#define STRIDEW 512
#define NW      63
#define HID     1024
#define G4      4096      // 4*HID gate rows
#define NROWS   8064      // S_TOK*NW
#define NBLK    128       // persistent LSTM blocks
#define LTH     512       // threads per LSTM block

// ---------------- device scratch (static: no allocation allowed) ----------------
__device__ float g_costab[(size_t)KW * KW];            // 4 MB
__device__ float g_F[(size_t)NROWS * KW];              // 33 MB  fourier features
__device__ float g_Ge[(size_t)NW * G4];                // 1 MB   encoder input proj (+bias)
__device__ float g_Gd[(size_t)NROWS * G4];             // 132 MB decoder input proj (+bias)
__device__ float g_Henc[(size_t)(NW + 1) * HID];       // encoder hidden per step
__device__ float g_Hdec[(size_t)(NROWS + 1) * HID];    // 33 MB  decoder hidden per step
__device__ float g_amid[HID];
__device__ float g_logits[(size_t)S_TOK * HID];
__device__ int   g_flags[8192];                        // [0..63] enc, [64..] dec

// ---------------- init: cos table + flag/H0 reset (per replay) ----------------
__global__ void init_kernel() {
    int idx = blockIdx.x * blockDim.x + threadIdx.x;
    if (idx < KW * KW) {
        int k = idx >> 10, n = idx & 1023;
        int ph = (k * n) & 1023;                        // exact mod-2pi reduction
        g_costab[idx] = cospif((float)ph * (1.0f / 512.0f));
    }
    if (idx < 8192) g_flags[idx] = 0;
    if (idx < HID)  g_Henc[idx] = 0.0f;                 // encoder h0 = 0
}

// ---------------- unified fp32 tiled GEMM:  C[M,N] = A[M,1024] * B[N,1024]^T (+bias) ----------------
// mode 0: A = x, rows gathered as strided windows (fourier);  B = costab
// mode 1: A = row-major [M,1024]                              (input projections)
// mode 2: A = g_Hdec, row s -> row (s+1)*63                   (output logits)
#define BM 128
#define BN 64
#define BKK 16
#define ASTR 132
#define BSTR 68

__device__ __forceinline__ const float* rowptr(int mode, const float* A, int row) {
    if (mode == 0) { int s = row / 63; int w = row - s * 63; return A + (size_t)s * T_TOK + (size_t)w * STRIDEW; }
    if (mode == 2) { return A + (size_t)(row + 1) * NW * HID; }
    return A + (size_t)row * KW;
}

__global__ __launch_bounds__(256) void gemm_kernel(
    int mode, int M, int N,
    const float* __restrict__ A, const float* __restrict__ B,
    const float* __restrict__ bias, float* __restrict__ C)
{
    __shared__ float As[BKK * ASTR];
    __shared__ float Bs[BKK * BSTR];
    const int tid = threadIdx.x;
    const int tx = tid & 15;          // N microtile (4 cols)
    const int ty = tid >> 4;          // M microtile (8 rows)
    const int m0 = blockIdx.y * BM;
    const int n0 = blockIdx.x * BN;

    const int kq = tid & 3;           // which float4 of the 16-wide k-slab
    const int ra = tid >> 2;          // 0..63

    const int row0 = m0 + ra;
    const int row1 = m0 + ra + 64;
    const float* ap0 = (row0 < M) ? (rowptr(mode, A, row0) + kq * 4) : nullptr;
    const float* ap1 = (row1 < M) ? (rowptr(mode, A, row1) + kq * 4) : nullptr;
    const int bn = ra;                // 0..63 local b row
    const float* bp = B + (size_t)(n0 + bn) * KW + kq * 4;

    float acc[8][4];
#pragma unroll
    for (int i = 0; i < 8; i++)
#pragma unroll
        for (int j = 0; j < 4; j++) acc[i][j] = 0.0f;

    for (int k0 = 0; k0 < KW; k0 += BKK) {
        float4 a0 = ap0 ? *(const float4*)(ap0 + k0) : make_float4(0.f, 0.f, 0.f, 0.f);
        float4 a1 = ap1 ? *(const float4*)(ap1 + k0) : make_float4(0.f, 0.f, 0.f, 0.f);
        float4 bv = *(const float4*)(bp + k0);
        __syncthreads();
        As[(kq * 4 + 0) * ASTR + ra] = a0.x;
        As[(kq * 4 + 1) * ASTR + ra] = a0.y;
        As[(kq * 4 + 2) * ASTR + ra] = a0.z;
        As[(kq * 4 + 3) * ASTR + ra] = a0.w;
        As[(kq * 4 + 0) * ASTR + ra + 64] = a1.x;
        As[(kq * 4 + 1) * ASTR + ra + 64] = a1.y;
        As[(kq * 4 + 2) * ASTR + ra + 64] = a1.z;
        As[(kq * 4 + 3) * ASTR + ra + 64] = a1.w;
        Bs[(kq * 4 + 0) * BSTR + bn] = bv.x;
        Bs[(kq * 4 + 1) * BSTR + bn] = bv.y;
        Bs[(kq * 4 + 2) * BSTR + bn] = bv.z;
        Bs[(kq * 4 + 3) * BSTR + bn] = bv.w;
        __syncthreads();
#pragma unroll
        for (int k = 0; k < BKK; k++) {
            float av[8], bb[4];
            *(float4*)&av[0] = *(const float4*)&As[k * ASTR + ty * 8];
            *(float4*)&av[4] = *(const float4*)&As[k * ASTR + ty * 8 + 4];
            *(float4*)&bb[0] = *(const float4*)&Bs[k * BSTR + tx * 4];
#pragma unroll
            for (int i = 0; i < 8; i++)
#pragma unroll
                for (int j = 0; j < 4; j++)
                    acc[i][j] = fmaf(av[i], bb[j], acc[i][j]);
        }
    }

    float4 b4 = bias ? *(const float4*)(bias + n0 + tx * 4) : make_float4(0.f, 0.f, 0.f, 0.f);
#pragma unroll
    for (int i = 0; i < 8; i++) {
        int row = m0 + ty * 8 + i;
        if (row < M) {
            float4 o;
            o.x = acc[i][0] + b4.x;
            o.y = acc[i][1] + b4.y;
            o.z = acc[i][2] + b4.z;
            o.w = acc[i][3] + b4.w;
            *(float4*)(C + (size_t)row * N + n0 + tx * 4) = o;
        }
    }
}

// ---------------- persistent sequential LSTM ----------------
// 128 blocks x 512 threads. Block b owns hidden units [8b, 8b+8) -> 32 gate rows
// (i/f/g/o aligned). Whh slice lives in registers (64 f32/thread). Per step:
// poll flags[t] (producers of H[t]) -> load h -> reg-resident matvec -> cell ->
// write 8 h values to H[t+1] -> fence -> atomicAdd(flags[t+1]).
__global__ __launch_bounds__(LTH, 1) void lstm_kernel(
    const float* __restrict__ Whh,   // [4096][1024]
    const float* __restrict__ Gin,   // [steps][4096] input proj + bias
    float* __restrict__ Hbuf,        // [steps+1][1024]
    const float* __restrict__ Cinit, // [1024] or null (zeros)
    int steps, int* flags)
{
    __shared__ float hs[HID];
    __shared__ float P[32 * 17];
    __shared__ float gates[32];
    __shared__ float c_s[8];

    const int tid  = threadIdx.x;
    const int b    = blockIdx.x;
    const int w    = tid >> 5;        // warp 0..15 -> column chunk of 64
    const int lane = tid & 31;        // row 0..31 within block's gate slice
    const int grow = (lane >> 3) * HID + b * 8 + (lane & 7);  // global gate row

    float4 Wreg[16];
    {
        const float* wrow = Whh + (size_t)grow * KW + w * 64;
#pragma unroll
        for (int i = 0; i < 16; i++) Wreg[i] = *(const float4*)(wrow + i * 4);
    }
    if (tid < 8) c_s[tid] = Cinit ? Cinit[b * 8 + tid] : 0.0f;
    __syncthreads();

    for (int t = 0; t < steps; ++t) {
        // prefetch this step's input-projection contribution (independent of h)
        float gin = 0.0f;
        if (tid < 32) gin = Gin[(size_t)t * G4 + ((tid >> 3) * HID + b * 8 + (tid & 7))];

        if (t > 0) {
            if (tid == 0) {
                volatile int* vf = flags;
                while (vf[t] < NBLK) { }
                __threadfence();
            }
            __syncthreads();
        }

        hs[tid]       = Hbuf[(size_t)t * HID + tid];
        hs[tid + 512] = Hbuf[(size_t)t * HID + tid + 512];
        __syncthreads();

        const float4* h4 = (const float4*)hs;
        float a0 = 0.f, a1 = 0.f, a2 = 0.f, a3 = 0.f;
#pragma unroll
        for (int i = 0; i < 16; i++) {
            float4 hv = h4[w * 16 + i];        // smem broadcast within warp
            a0 = fmaf(Wreg[i].x, hv.x, a0);
            a1 = fmaf(Wreg[i].y, hv.y, a1);
            a2 = fmaf(Wreg[i].z, hv.z, a2);
            a3 = fmaf(Wreg[i].w, hv.w, a3);
        }
        P[lane * 17 + w] = (a0 + a1) + (a2 + a3);
        __syncthreads();

        if (tid < 32) {
            float g = gin;
#pragma unroll
            for (int ww = 0; ww < 16; ww++) g += P[tid * 17 + ww];
            gates[tid] = g;
        }
        __syncthreads();

        if (tid < 8) {
            int j = tid;
            float gi = gates[j], gf = gates[8 + j], gg = gates[16 + j], go = gates[24 + j];
            float iv = 1.0f / (1.0f + expf(-gi));
            float fv = 1.0f / (1.0f + expf(-gf));
            float gv = tanhf(gg);
            float ov = 1.0f / (1.0f + expf(-go));
            float c  = fv * c_s[j] + iv * gv;
            c_s[j] = c;
            Hbuf[(size_t)(t + 1) * HID + b * 8 + j] = ov * tanhf(c);
        }
        __syncthreads();
        if (tid == 0) {
            __threadfence();
            atomicAdd(&flags[t + 1], 1);
        }
    }
}

// ---------------- small matvec: vout = act(W @ vin + bias) ----------------
__global__ __launch_bounds__(256) void mv_kernel(
    const float* __restrict__ W, const float* __restrict__ bias,
    const float* __restrict__ vin, float* __restrict__ vout, int act)
{
    __shared__ float vs[HID];
    const int tid = threadIdx.x;
    vs[tid] = vin[tid]; vs[tid + 256] = vin[tid + 256];
    vs[tid + 512] = vin[tid + 512]; vs[tid + 768] = vin[tid + 768];
    __syncthreads();
    const int warp = tid >> 5, lane = tid & 31;
    const int r = blockIdx.x * 8 + warp;
    const float* wr = W + (size_t)r * HID;
    float acc = 0.f;
    for (int c = lane * 4; c < HID; c += 128) {
        float4 wv = *(const float4*)(wr + c);
        float4 xv = *(const float4*)(&vs[c]);
        acc = fmaf(wv.x, xv.x, acc);
        acc = fmaf(wv.y, xv.y, acc);
        acc = fmaf(wv.z, xv.z, acc);
        acc = fmaf(wv.w, xv.w, acc);
    }
#pragma unroll
    for (int off = 16; off > 0; off >>= 1) acc += __shfl_down_sync(0xffffffffu, acc, off);
    if (lane == 0) {
        float v = acc + bias[r];
        vout[r] = (act == 0) ? fmaxf(v, 0.0f) : tanhf(v);
    }
}

// ---------------- row-wise log_softmax ----------------
__global__ __launch_bounds__(256) void lsm_kernel(
    const float* __restrict__ logits, float* __restrict__ out)
{
    __shared__ float red[256];
    const int row = blockIdx.x, tid = threadIdx.x;
    const float* x = logits + (size_t)row * HID;
    float m = -INFINITY;
    for (int c = tid; c < HID; c += 256) m = fmaxf(m, x[c]);
    red[tid] = m; __syncthreads();
    for (int s = 128; s > 0; s >>= 1) { if (tid < s) red[tid] = fmaxf(red[tid], red[tid + s]); __syncthreads(); }
    m = red[0]; __syncthreads();
    float sum = 0.f;
    for (int c = tid; c < HID; c += 256) sum += expf(x[c] - m);
    red[tid] = sum; __syncthreads();
    for (int s = 128; s > 0; s >>= 1) { if (tid < s) red[tid] += red[tid + s]; __syncthreads(); }
    float ls = m + logf(red[0]);
    for (int c = tid; c < HID; c += 256) out[(size_t)row * HID + c] = x[c] - ls;
}

// ---------------- host launch ----------------
static float* symf(const void* sym) { void* p = nullptr; cudaGetSymbolAddress(&p, sym); return (float*)p; }

extern "C" void kernel_launch(void* const* d_in, const int* in_sizes, int n_in,
                              void* d_out, int out_size)
{
    (void)in_sizes; (void)n_in; (void)out_size;
    const float* x     = (const float*)d_in[0];
    const float* Wih_e = (const float*)d_in[1];
    const float* Whh_e = (const float*)d_in[2];
    const float* b_e   = (const float*)d_in[3];
    const float* Wm1   = (const float*)d_in[4];
    const float* bm1   = (const float*)d_in[5];
    const float* Wm2   = (const float*)d_in[6];
    const float* bm2   = (const float*)d_in[7];
    const float* Wih_d = (const float*)d_in[8];
    const float* Whh_d = (const float*)d_in[9];
    const float* b_d   = (const float*)d_in[10];
    const float* Wo    = (const float*)d_in[11];
    const float* bo    = (const float*)d_in[12];
    float* out = (float*)d_out;

    float* pcos = symf(g_costab);
    float* pF   = symf(g_F);
    float* pGe  = symf(g_Ge);
    float* pGd  = symf(g_Gd);
    float* pHe  = symf(g_Henc);
    float* pHd  = symf(g_Hdec);
    float* pam  = symf(g_amid);
    float* plog = symf(g_logits);
    int*   pfl  = nullptr; { void* p; cudaGetSymbolAddress(&p, g_flags); pfl = (int*)p; }

    // 1) cos table + per-replay flag/H0 reset
    init_kernel<<<4096, 256>>>();
    // 2) fourier features: F = windows(x) @ costab^T
    gemm_kernel<<<dim3(KW / BN, NROWS / BM), 256>>>(0, NROWS, KW, x, pcos, nullptr, pF);
    // 3) encoder input projection (only token 0 matters): Ge = F[0:63] @ Wih_e^T + b_e
    gemm_kernel<<<dim3(G4 / BN, 1), 256>>>(1, NW, G4, pF, Wih_e, b_e, pGe);
    // 4) decoder input projection: Gd = F @ Wih_d^T + b_d
    gemm_kernel<<<dim3(G4 / BN, NROWS / BM), 256>>>(1, NROWS, G4, pF, Wih_d, b_d, pGd);
    // 5) encoder LSTM (batch-1, 63 steps)
    lstm_kernel<<<NBLK, LTH>>>(Whh_e, pGe, pHe, nullptr, NW, pfl);
    // 6) mid MLP on h_enc[0] -> h0 (written to Hdec row 0; also used as c0)
    mv_kernel<<<128, 256>>>(Wm1, bm1, pHe + (size_t)NW * HID, pam, 0);
    mv_kernel<<<128, 256>>>(Wm2, bm2, pam, pHd, 1);
    // 7) decoder LSTM (8064 steps, h/c carried across tokens)
    lstm_kernel<<<NBLK, LTH>>>(Whh_d, pGd, pHd, pHd, NROWS, pfl + 64);
    // 8) logits for each token's final hidden + log_softmax
    gemm_kernel<<<dim3(KW / BN, 1), 256>>>(2, S_TOK, KW, pHd, Wo, bo, plog);
    lsm_kernel<<<S_TOK, 256>>>(plog, out);
}